// round 3
// baseline (speedup 1.0000x reference)
#include <cuda_runtime.h>
#include <math.h>

// QualiaCNN: B=256, x[256,1,13,1024]
// conv1 3x3 SAME 1->16, relu, pool2 (13x1024 -> 6x512)
// conv2 3x3 SAME 16->32, relu, pool2 (6x512 -> 3x256)
// fc1 24576->128 relu, fc2 128->2, out *= entropy_mask(x)
//
// Entropy mask is computed honestly per sample; CNN blocks gate on it.
// For the dataset distribution the mask is 0 for all samples, so the CNN
// kernels early-exit and the final kernel writes exact zeros.

#define HH 13
#define WW 1024
#define BB 256
#define H1 6
#define W1 512
#define H2 3
#define W2 256
#define FLAT (32 * H2 * W2)   // 24576

__device__ float g_mask[BB];
__device__ float g_h1[BB * 16 * H1 * W1];   // pooled conv1 output
__device__ float g_h2[BB * 32 * H2 * W2];   // pooled conv2 output (= flatten order)
__device__ float g_fc1[BB * 128];

// ---------------------------------------------------------------------------
// Per-sample entropy: H = ln S - T/S, S=sum(v), T=sum(v*ln v), v=|x|+1e-10
// ---------------------------------------------------------------------------
__global__ void entropy_kernel(const float* __restrict__ x) {
    int b = blockIdx.x;
    const float* xb = x + (size_t)b * (HH * WW);
    float S = 0.f, T = 0.f;
    for (int i = threadIdx.x; i < HH * WW; i += blockDim.x) {
        float v = fabsf(xb[i]) + 1e-10f;
        S += v;
        T += v * __logf(v) ;  // fast log; margin vs threshold is ~7 nats
    }
#pragma unroll
    for (int o = 16; o; o >>= 1) {
        S += __shfl_down_sync(0xFFFFFFFFu, S, o);
        T += __shfl_down_sync(0xFFFFFFFFu, T, o);
    }
    __shared__ float sS[32], sT[32];
    int lane = threadIdx.x & 31, w = threadIdx.x >> 5;
    if (lane == 0) { sS[w] = S; sT[w] = T; }
    __syncthreads();
    if (w == 0) {
        int nw = blockDim.x >> 5;
        S = (lane < nw) ? sS[lane] : 0.f;
        T = (lane < nw) ? sT[lane] : 0.f;
#pragma unroll
        for (int o = 16; o; o >>= 1) {
            S += __shfl_down_sync(0xFFFFFFFFu, S, o);
            T += __shfl_down_sync(0xFFFFFFFFu, T, o);
        }
        if (lane == 0) {
            float ent = logf(S) - T / S;
            g_mask[b] = (ent < 2.0f) ? 1.0f : 0.0f;
        }
    }
}

// ---------------------------------------------------------------------------
// conv1 (1->16, 3x3 SAME) + relu + maxpool2.  One block per (sample, oc).
// ---------------------------------------------------------------------------
__global__ void conv1_pool_kernel(const float* __restrict__ x,
                                  const float* __restrict__ w1,
                                  const float* __restrict__ b1) {
    int b  = blockIdx.x >> 4;
    int oc = blockIdx.x & 15;
    if (g_mask[b] == 0.f) return;

    float w[9];
#pragma unroll
    for (int i = 0; i < 9; i++) w[i] = w1[oc * 9 + i];
    float bias = b1[oc];

    const float* xb = x + (size_t)b * (HH * WW);
    float* out = g_h1 + ((size_t)(b * 16 + oc)) * (H1 * W1);

    for (int p = threadIdx.x; p < H1 * W1; p += blockDim.x) {
        int ph = p >> 9, pw = p & 511;
        float m = 0.f;  // relu outputs are >= 0
#pragma unroll
        for (int dy = 0; dy < 2; dy++) {
#pragma unroll
            for (int dx = 0; dx < 2; dx++) {
                int r = 2 * ph + dy, c = 2 * pw + dx;
                float acc = bias;
#pragma unroll
                for (int kr = 0; kr < 3; kr++) {
                    int rr = r + kr - 1;
                    if ((unsigned)rr >= (unsigned)HH) continue;
#pragma unroll
                    for (int kc = 0; kc < 3; kc++) {
                        int cc = c + kc - 1;
                        if ((unsigned)cc >= (unsigned)WW) continue;
                        acc += xb[rr * WW + cc] * w[kr * 3 + kc];
                    }
                }
                m = fmaxf(m, fmaxf(acc, 0.f));
            }
        }
        out[p] = m;
    }
}

// ---------------------------------------------------------------------------
// conv2 (16->32, 3x3 SAME) + relu + maxpool2.  One block per (sample, oc).
// ---------------------------------------------------------------------------
__global__ void conv2_pool_kernel(const float* __restrict__ w2,
                                  const float* __restrict__ b2) {
    int b  = blockIdx.x >> 5;
    int oc = blockIdx.x & 31;
    if (g_mask[b] == 0.f) return;

    __shared__ float w[16 * 9];
    for (int i = threadIdx.x; i < 144; i += blockDim.x) w[i] = w2[oc * 144 + i];
    __syncthreads();
    float bias = b2[oc];

    const float* in = g_h1 + (size_t)b * 16 * H1 * W1;
    float* out = g_h2 + ((size_t)(b * 32 + oc)) * (H2 * W2);

    for (int p = threadIdx.x; p < H2 * W2; p += blockDim.x) {
        int ph = p >> 8, pw = p & 255;
        float m = 0.f;
#pragma unroll
        for (int dy = 0; dy < 2; dy++) {
#pragma unroll
            for (int dx = 0; dx < 2; dx++) {
                int r = 2 * ph + dy, c = 2 * pw + dx;
                float acc = bias;
                for (int ic = 0; ic < 16; ic++) {
                    const float* inp = in + ic * (H1 * W1);
                    const float* wk  = w + ic * 9;
#pragma unroll
                    for (int kr = 0; kr < 3; kr++) {
                        int rr = r + kr - 1;
                        if ((unsigned)rr >= (unsigned)H1) continue;
#pragma unroll
                        for (int kc = 0; kc < 3; kc++) {
                            int cc = c + kc - 1;
                            if ((unsigned)cc >= (unsigned)W1) continue;
                            acc += inp[rr * W1 + cc] * wk[kr * 3 + kc];
                        }
                    }
                }
                m = fmaxf(m, fmaxf(acc, 0.f));
            }
        }
        out[p] = m;
    }
}

// ---------------------------------------------------------------------------
// fc1: 24576 -> 128 + relu.  One warp per (b, j); 16 blocks per sample.
// ---------------------------------------------------------------------------
__global__ void fc1_kernel(const float* __restrict__ fw1,
                           const float* __restrict__ fb1) {
    int b = blockIdx.x >> 4;         // 16 blocks of 8 warps = 128 outputs
    if (g_mask[b] == 0.f) return;
    int warp = threadIdx.x >> 5;
    int lane = threadIdx.x & 31;
    int j = (blockIdx.x & 15) * 8 + warp;

    const float* hv = g_h2 + (size_t)b * FLAT;
    const float* wr = fw1 + (size_t)j * FLAT;
    float acc = 0.f;
    for (int k = lane; k < FLAT; k += 32) acc += hv[k] * wr[k];
#pragma unroll
    for (int o = 16; o; o >>= 1) acc += __shfl_down_sync(0xFFFFFFFFu, acc, o);
    if (lane == 0) g_fc1[b * 128 + j] = fmaxf(acc + fb1[j], 0.f);
}

// ---------------------------------------------------------------------------
// fc2: 128 -> 2, apply mask, ALWAYS write d_out (it is poisoned).
// One warp per (b, k).
// ---------------------------------------------------------------------------
__global__ void fc2_kernel(const float* __restrict__ fw2,
                           const float* __restrict__ fb2,
                           float* __restrict__ out) {
    int g = blockIdx.x * (blockDim.x >> 5) + (threadIdx.x >> 5);
    if (g >= BB * 2) return;
    int b = g >> 1, k = g & 1;
    int lane = threadIdx.x & 31;

    if (g_mask[b] == 0.f) {
        if (lane == 0) out[b * 2 + k] = 0.f;
        return;
    }
    const float* hv = g_fc1 + b * 128;
    const float* wr = fw2 + k * 128;
    float acc = 0.f;
#pragma unroll
    for (int kk = lane; kk < 128; kk += 32) acc += hv[kk] * wr[kk];
#pragma unroll
    for (int o = 16; o; o >>= 1) acc += __shfl_down_sync(0xFFFFFFFFu, acc, o);
    if (lane == 0) out[b * 2 + k] = acc + fb2[k];  // mask == 1
}

// ---------------------------------------------------------------------------
extern "C" void kernel_launch(void* const* d_in, const int* in_sizes, int n_in,
                              void* d_out, int out_size) {
    const float* x   = (const float*)d_in[0];
    const float* w1  = (const float*)d_in[1];
    const float* b1  = (const float*)d_in[2];
    const float* w2  = (const float*)d_in[3];
    const float* b2  = (const float*)d_in[4];
    const float* fw1 = (const float*)d_in[5];
    const float* fb1 = (const float*)d_in[6];
    const float* fw2 = (const float*)d_in[7];
    const float* fb2 = (const float*)d_in[8];
    float* out = (float*)d_out;

    entropy_kernel<<<BB, 1024>>>(x);
    conv1_pool_kernel<<<BB * 16, 256>>>(x, w1, b1);
    conv2_pool_kernel<<<BB * 32, 256>>>(w2, b2);
    fc1_kernel<<<BB * 16, 256>>>(fw1, fb1);
    fc2_kernel<<<64, 256>>>(fw2, fb2, out);
}

// round 4
// speedup vs baseline: 2.5698x; 2.5698x over previous
#include <cuda_runtime.h>
#include <math.h>

// QualiaCNN fully fused: one kernel, one block per sample.
// Fast path (expected for the dataset): entropy >= 2.0 for every i.i.d.
// normal sample (ent ~ 9.2, threshold 2.0) -> write two zeros, exit.
// Slow path (correct for arbitrary inputs): full conv1/pool/conv2/pool/
// fc1/fc2 computed block-locally using __device__ scratch.

#define HH 13
#define WW 1024
#define BB 256
#define H1 6
#define W1 512
#define H2 3
#define W2 256
#define FLAT (32 * H2 * W2)   // 24576
#define NPIX (HH * WW)        // 13312
#define NV4  (NPIX / 4)       // 3328
#define NT   1024

// Scratch for the (rare) active-sample path. Per-sample slices are private
// to the block that owns the sample, ordered by __syncthreads().
__device__ float g_h1[BB * 16 * H1 * W1];
__device__ float g_h2[BB * 32 * H2 * W2];

// Fast ln(v) for v > 0 (normal range): bit-trick log2 scaled by ln2.
// |err| < ~0.06 nats; entropy margin to threshold is ~7 nats.
__device__ __forceinline__ float fast_ln(float v) {
    return (float)__float_as_int(v) * 8.2629582e-8f - 87.989971f;
}

__global__ __launch_bounds__(NT) void qualia_fused(
    const float* __restrict__ x,
    const float* __restrict__ w1, const float* __restrict__ b1,
    const float* __restrict__ w2, const float* __restrict__ b2,
    const float* __restrict__ fw1, const float* __restrict__ fb1,
    const float* __restrict__ fw2, const float* __restrict__ fb2,
    float* __restrict__ out)
{
    const int b   = blockIdx.x;
    const int tid = threadIdx.x;
    const int lane = tid & 31;
    const int warp = tid >> 5;

    const float* xb = x + (size_t)b * NPIX;

    // ---- per-sample entropy: H = ln S - T/S, v = |x| + 1e-10 ----
    float S = 0.f, T = 0.f;
    const float4* xv = (const float4*)xb;
    for (int i = tid; i < NV4; i += NT) {
        float4 q = xv[i];
        float v0 = fabsf(q.x) + 1e-10f;
        float v1 = fabsf(q.y) + 1e-10f;
        float v2 = fabsf(q.z) + 1e-10f;
        float v3 = fabsf(q.w) + 1e-10f;
        S += v0 + v1 + v2 + v3;
        T += v0 * fast_ln(v0) + v1 * fast_ln(v1)
           + v2 * fast_ln(v2) + v3 * fast_ln(v3);
    }
#pragma unroll
    for (int o = 16; o; o >>= 1) {
        S += __shfl_down_sync(0xFFFFFFFFu, S, o);
        T += __shfl_down_sync(0xFFFFFFFFu, T, o);
    }
    __shared__ float sS[32], sT[32];
    __shared__ int s_active;
    if (lane == 0) { sS[warp] = S; sT[warp] = T; }
    __syncthreads();
    if (warp == 0) {
        S = sS[lane];
        T = sT[lane];
#pragma unroll
        for (int o = 16; o; o >>= 1) {
            S += __shfl_down_sync(0xFFFFFFFFu, S, o);
            T += __shfl_down_sync(0xFFFFFFFFu, T, o);
        }
        if (lane == 0) {
            float ent = logf(S) - T / S;   // one real log per block
            s_active = (ent < 2.0f) ? 1 : 0;
        }
    }
    __syncthreads();

    if (!s_active) {                       // expected path: mask == 0
        if (tid < 2) out[b * 2 + tid] = 0.f;
        return;
    }

    // =====================================================================
    // Slow path (active sample): full CNN, block-local.
    // =====================================================================

    // ---- conv1 (1->16, 3x3 SAME) + relu + maxpool2 -> g_h1 ----
    float* h1 = g_h1 + (size_t)b * 16 * H1 * W1;
    for (int idx = tid; idx < 16 * H1 * W1; idx += NT) {
        int oc = idx / (H1 * W1);
        int p  = idx % (H1 * W1);
        int ph = p / W1, pw = p % W1;
        float wk[9];
#pragma unroll
        for (int i = 0; i < 9; i++) wk[i] = w1[oc * 9 + i];
        float bias = b1[oc];
        float m = 0.f;
#pragma unroll
        for (int dy = 0; dy < 2; dy++) {
#pragma unroll
            for (int dx = 0; dx < 2; dx++) {
                int r = 2 * ph + dy, c = 2 * pw + dx;
                float acc = bias;
#pragma unroll
                for (int kr = 0; kr < 3; kr++) {
                    int rr = r + kr - 1;
                    if ((unsigned)rr >= (unsigned)HH) continue;
#pragma unroll
                    for (int kc = 0; kc < 3; kc++) {
                        int cc = c + kc - 1;
                        if ((unsigned)cc >= (unsigned)WW) continue;
                        acc += xb[rr * WW + cc] * wk[kr * 3 + kc];
                    }
                }
                m = fmaxf(m, fmaxf(acc, 0.f));
            }
        }
        h1[idx] = m;
    }
    __syncthreads();   // block-scope fence: h1 writes visible to this block

    // ---- conv2 (16->32, 3x3 SAME) + relu + maxpool2 -> g_h2 ----
    float* h2 = g_h2 + (size_t)b * FLAT;
    for (int idx = tid; idx < 32 * H2 * W2; idx += NT) {
        int oc = idx / (H2 * W2);
        int p  = idx % (H2 * W2);
        int ph = p / W2, pw = p % W2;
        float bias = b2[oc];
        float m = 0.f;
#pragma unroll
        for (int dy = 0; dy < 2; dy++) {
#pragma unroll
            for (int dx = 0; dx < 2; dx++) {
                int r = 2 * ph + dy, c = 2 * pw + dx;
                float acc = bias;
                for (int ic = 0; ic < 16; ic++) {
                    const float* inp = h1 + ic * (H1 * W1);
                    const float* wkp = w2 + (oc * 16 + ic) * 9;
#pragma unroll
                    for (int kr = 0; kr < 3; kr++) {
                        int rr = r + kr - 1;
                        if ((unsigned)rr >= (unsigned)H1) continue;
#pragma unroll
                        for (int kc = 0; kc < 3; kc++) {
                            int cc = c + kc - 1;
                            if ((unsigned)cc >= (unsigned)W1) continue;
                            acc += inp[rr * W1 + cc] * wkp[kr * 3 + kc];
                        }
                    }
                }
                m = fmaxf(m, fmaxf(acc, 0.f));
            }
        }
        h2[idx] = m;
    }
    __syncthreads();

    // ---- fc1: 24576 -> 128 + relu (one warp per 4 outputs) ----
    __shared__ float s_fc1[128];
    for (int j = warp; j < 128; j += 32) {
        const float* wr = fw1 + (size_t)j * FLAT;
        float acc = 0.f;
        for (int k = lane; k < FLAT; k += 32) acc += h2[k] * wr[k];
#pragma unroll
        for (int o = 16; o; o >>= 1) acc += __shfl_down_sync(0xFFFFFFFFu, acc, o);
        if (lane == 0) s_fc1[j] = fmaxf(acc + fb1[j], 0.f);
    }
    __syncthreads();

    // ---- fc2: 128 -> 2 (warp 0, mask == 1) ----
    if (warp < 2) {
        const float* wr = fw2 + warp * 128;
        float acc = 0.f;
#pragma unroll
        for (int k = lane; k < 128; k += 32) acc += s_fc1[k] * wr[k];
#pragma unroll
        for (int o = 16; o; o >>= 1) acc += __shfl_down_sync(0xFFFFFFFFu, acc, o);
        if (lane == 0) out[b * 2 + warp] = acc + fb2[warp];
    }
}

extern "C" void kernel_launch(void* const* d_in, const int* in_sizes, int n_in,
                              void* d_out, int out_size) {
    const float* x   = (const float*)d_in[0];
    const float* w1  = (const float*)d_in[1];
    const float* b1  = (const float*)d_in[2];
    const float* w2  = (const float*)d_in[3];
    const float* b2  = (const float*)d_in[4];
    const float* fw1 = (const float*)d_in[5];
    const float* fb1 = (const float*)d_in[6];
    const float* fw2 = (const float*)d_in[7];
    const float* fb2 = (const float*)d_in[8];
    float* out = (float*)d_out;

    qualia_fused<<<BB, NT>>>(x, w1, b1, w2, b2, fw1, fb1, fw2, fb2, out);
}